// round 9
// baseline (speedup 1.0000x reference)
#include <cuda_runtime.h>
#include <cuda_bf16.h>
#include <math_constants.h>
#include <cstdint>

#define H 128
#define NPAD 1048576
#define SEG_CAP 65536

#define RST32 528                        // fp32 stage row stride bytes (132 floats)
#define RSTB  144                        // bf16 B row stride bytes (72 elems)
#define A32_BUF 33792                    // 64 x 528

// smem layout (bytes), per CTA (x2 CTAs/SM)
#define OFF_B_HI  0                      // 128 x 144 = 18432
#define OFF_B_LO  18432
#define OFF_A32   36864                  // 2 bufs x 33792 = 67584
#define OFF_SGATE 104448                 // 128 floats = 512
#define OFF_SB1   104960                 // 256
#define OFF_SW2   105216                 // 256
#define SMEM_TOTAL 105472

__device__ float d_gate2[2 * NPAD];
__device__ int   d_seg_start[SEG_CAP];
__device__ int   d_seg_end[SEG_CAP];
__device__ __nv_bfloat16 d_W1hi[H * H];
__device__ __nv_bfloat16 d_W1lo[H * H];

// ---------------------------------------------------------------------------
__device__ __forceinline__ uint32_t smem_u32(const void* p) {
    uint32_t a;
    asm("{ .reg .u64 t; cvta.to.shared.u64 t, %1; cvt.u32.u64 %0, t; }"
        : "=r"(a) : "l"(p));
    return a;
}
__device__ __forceinline__ void ldsm_x4_t(uint32_t* r, uint32_t addr) {
    asm volatile("ldmatrix.sync.aligned.m8n8.x4.trans.shared.b16 {%0,%1,%2,%3}, [%4];"
                 : "=r"(r[0]), "=r"(r[1]), "=r"(r[2]), "=r"(r[3]) : "r"(addr));
}
__device__ __forceinline__ void mma16816(float* d, const uint32_t* a,
                                         const uint32_t* b) {
    asm volatile(
        "mma.sync.aligned.m16n8k16.row.col.f32.bf16.bf16.f32 "
        "{%0,%1,%2,%3}, {%4,%5,%6,%7}, {%8,%9}, {%0,%1,%2,%3};"
        : "+f"(d[0]), "+f"(d[1]), "+f"(d[2]), "+f"(d[3])
        : "r"(a[0]), "r"(a[1]), "r"(a[2]), "r"(a[3]), "r"(b[0]), "r"(b[1]));
}
__device__ __forceinline__ void cp_async16(uint32_t dst, const void* src, int sz) {
    asm volatile("cp.async.cg.shared.global [%0], [%1], 16, %2;"
                 :: "r"(dst), "l"(src), "r"(sz) : "memory");
}
#define CP_COMMIT() asm volatile("cp.async.commit_group;" ::: "memory")
#define CP_WAIT0()  asm volatile("cp.async.wait_group 0;" ::: "memory")
#define CP_WAIT1()  asm volatile("cp.async.wait_group 1;" ::: "memory")

__device__ __forceinline__ float2 lds_f2(uint32_t addr) {
    float2 v;
    asm volatile("ld.shared.v2.f32 {%0,%1}, [%2];"
                 : "=f"(v.x), "=f"(v.y) : "r"(addr));
    return v;
}
__device__ __forceinline__ uint32_t pack_hi(float2 v) {
    __nv_bfloat162 h = __floats2bfloat162_rn(v.x, v.y);
    return *(uint32_t*)&h;
}
__device__ __forceinline__ uint32_t pack_lo(float2 v, uint32_t hiP) {
    __nv_bfloat162 h = *(__nv_bfloat162*)&hiP;
    __nv_bfloat162 l = __floats2bfloat162_rn(v.x - __bfloat162float(h.x),
                                             v.y - __bfloat162float(h.y));
    return *(uint32_t*)&l;
}

// ---------------------------------------------------------------------------
// Segment bounds
// ---------------------------------------------------------------------------
__global__ void init_bounds_kernel(int B) {
    int b = blockIdx.x * blockDim.x + threadIdx.x;
    if (b < B) { d_seg_start[b] = -1; d_seg_end[b] = -1; }
}
__global__ void bounds_kernel(const int* __restrict__ bi, int N) {
    int n = blockIdx.x * blockDim.x + threadIdx.x;
    if (n >= N) return;
    int b = bi[n];
    if (n == 0 || bi[n - 1] != b) d_seg_start[b] = n;
    if (n == N - 1 || bi[n + 1] != b) d_seg_end[b] = n + 1;
}

// ---------------------------------------------------------------------------
// W1 -> bf16 hi/lo split (runs once)
// ---------------------------------------------------------------------------
__global__ void prep_w1_kernel(const float* __restrict__ W1) {
    int idx = blockIdx.x * blockDim.x + threadIdx.x;
    if (idx >= H * H) return;
    float v = W1[idx];
    __nv_bfloat16 hi = __float2bfloat16(v);
    __nv_bfloat16 lo = __float2bfloat16(v - __bfloat162float(hi));
    d_W1hi[idx] = hi;
    d_W1lo[idx] = lo;
}

__device__ __forceinline__ void issue_cp(const float* __restrict__ x, uint32_t sb,
                                         long t, int buf, int N, int tid) {
    long m0 = t * 64;
    uint32_t dst0 = sb + OFF_A32 + buf * A32_BUF;
#pragma unroll
    for (int c = 0; c < 8; c++) {
        int chunk = c * 256 + tid;           // 2048 chunks of 16B
        int row = chunk >> 5, col16 = chunk & 31;
        long gm = m0 + row;
        const float* src = x + (size_t)(gm < N ? gm : 0) * H + col16 * 4;
        cp_async16(dst0 + row * RST32 + col16 * 16, src, gm < N ? 16 : 0);
    }
    CP_COMMIT();
}

// ---------------------------------------------------------------------------
// Gate kernel: persistent, 2 CTAs/SM. CTA = (64-row tile, 64-col half).
// 256 thr = 8 warps (4M x 2N), warp tile 16x32. A fragments built in-register
// from the cp.async fp32 stage (LDS.64 + cvt inside the k-loop); B (W1 half,
// bf16 hi/lo) in smem via ldmatrix. Split accumulators shorten RAW chains.
// ---------------------------------------------------------------------------
__global__ __launch_bounds__(256, 2) void gate_mma_kernel(
    const float* __restrict__ x, const float* __restrict__ b1,
    const float* __restrict__ W2, int N)
{
    extern __shared__ char smem[];
    const uint32_t sb = smem_u32(smem);
    const int tid = threadIdx.x;
    const int wid = tid >> 5, lane = tid & 31;
    const int warp_m = wid & 3;          // rows warp_m*16
    const int warp_n = wid >> 2;         // local cols warp_n*32
    const int half = blockIdx.x & 1;
    const long tile0 = blockIdx.x >> 1;
    const long tstride = gridDim.x >> 1;

    float* sgate = (float*)(smem + OFF_SGATE);
    float* sb1   = (float*)(smem + OFF_SB1);
    float* sw2   = (float*)(smem + OFF_SW2);
    if (tid < 64) {
        sb1[tid] = b1[half * 64 + tid];
        sw2[tid] = W2[half * 64 + tid];
    }

    const int numTiles = (N + 63) / 64;

    // prologue cp for t0
    if (tile0 < numTiles) issue_cp(x, sb, tile0, 0, N, tid);

    // B half (W1 hi/lo) -> smem once: 128 rows x 8 uint4 per matrix
#pragma unroll
    for (int c = 0; c < 4; c++) {
        int idx = c * 256 + tid;             // 1024 uint4 per matrix
        int k = idx >> 3, n8 = (idx & 7) << 3;
        uint32_t off = (uint32_t)k * RSTB + (uint32_t)n8 * 2;
        *(uint4*)(smem + OFF_B_HI + off) = *(const uint4*)(d_W1hi + k * H + half * 64 + n8);
        *(uint4*)(smem + OFF_B_LO + off) = *(const uint4*)(d_W1lo + k * H + half * 64 + n8);
    }

    if (tile0 + tstride < numTiles) issue_cp(x, sb, tile0 + tstride, 1, N, tid);

    // per-lane addresses
    const int fr = lane >> 2;            // 0..7
    const int fc = (lane & 3) * 2;       // 0,2,4,6
    const uint32_t a_base = sb + OFF_A32
                          + (uint32_t)(warp_m * 16 + fr) * RST32 + (uint32_t)fc * 4;
    const uint32_t b_base = sb + (uint32_t)(lane & 15) * RSTB
                          + (uint32_t)(warp_n * 32 + (lane >> 4) * 8) * 2;

    int buf = 0;
    for (long t = tile0; t < numTiles; t += tstride, buf ^= 1) {
        const bool hn  = (t + tstride)     < numTiles;
        const bool hnn = (t + 2 * tstride) < numTiles;

        if (hn) { CP_WAIT1(); } else { CP_WAIT0(); }
        __syncthreads();                 // A32[buf] visible; sgate free

        // ---- MMA k-loop with in-register A convert ----
        float accH[4][4], accL[4][4];
#pragma unroll
        for (int ni = 0; ni < 4; ni++)
#pragma unroll
            for (int r = 0; r < 4; r++) { accH[ni][r] = 0.f; accL[ni][r] = 0.f; }

        const uint32_t aK = a_base + (uint32_t)buf * A32_BUF;
#pragma unroll
        for (int k = 0; k < 8; k++) {
            // A fragment: rows {fr, fr+8}, k-cols {fc, fc+1, fc+8, fc+9}
            const uint32_t ak = aK + (uint32_t)k * 64;   // 16 floats per k-step
            float2 f00 = lds_f2(ak);
            float2 f10 = lds_f2(ak + 8 * RST32);
            float2 f01 = lds_f2(ak + 32);
            float2 f11 = lds_f2(ak + 8 * RST32 + 32);
            uint32_t ah[4], al[4];
            ah[0] = pack_hi(f00); al[0] = pack_lo(f00, ah[0]);
            ah[1] = pack_hi(f10); al[1] = pack_lo(f10, ah[1]);
            ah[2] = pack_hi(f01); al[2] = pack_lo(f01, ah[2]);
            ah[3] = pack_hi(f11); al[3] = pack_lo(f11, ah[3]);

#pragma unroll
            for (int nb = 0; nb < 2; nb++) {
                uint32_t bh[4], bl[4];
                uint32_t bo = b_base + (uint32_t)k * 16 * RSTB + nb * 32;
                ldsm_x4_t(bh, bo + OFF_B_HI);
                ldsm_x4_t(bl, bo + OFF_B_LO);
                mma16816(accH[nb * 2],     ah, &bh[0]);
                mma16816(accH[nb * 2 + 1], ah, &bh[2]);
                mma16816(accL[nb * 2],     al, &bh[0]);
                mma16816(accL[nb * 2 + 1], al, &bh[2]);
                mma16816(accL[nb * 2],     ah, &bl[0]);
                mma16816(accL[nb * 2 + 1], ah, &bl[2]);
            }
        }

        // ---- epilogue: silu + dot(W2 slice), warp row-reduce ----
        float part[2] = {0.f, 0.f};
#pragma unroll
        for (int ni = 0; ni < 4; ni++)
#pragma unroll
            for (int r = 0; r < 4; r++) {
                int col = warp_n * 32 + ni * 8 + (lane & 3) * 2 + (r & 1);
                float vv = accH[ni][r] + accL[ni][r] + sb1[col];
                float sl = vv / (1.f + __expf(-vv));
                part[r >> 1] = fmaf(sl, sw2[col], part[r >> 1]);
            }
#pragma unroll
        for (int hh = 0; hh < 2; hh++) {
            float p = part[hh];
            p += __shfl_xor_sync(0xFFFFFFFF, p, 1);
            p += __shfl_xor_sync(0xFFFFFFFF, p, 2);
            part[hh] = p;
        }
        if ((lane & 3) == 0) {
#pragma unroll
            for (int hh = 0; hh < 2; hh++) {
                int row = warp_m * 16 + hh * 8 + (lane >> 2);
                sgate[warp_n * 64 + row] = part[hh];
            }
        }
        __syncthreads();                 // A32[buf] reads done; sgate complete

        // refill this buffer for t+2 (overlaps next iteration's MMA on buf^1)
        if (hnn) issue_cp(x, sb, t + 2 * tstride, buf, N, tid);

        if (tid < 64) {
            long gm = t * 64 + tid;
            if (gm < N)
                d_gate2[(size_t)half * NPAD + gm] = sgate[tid] + sgate[64 + tid];
        }
    }
}

// ---------------------------------------------------------------------------
// Reduce kernel: per-segment mean/max/attention (b2 cancels in softmax)
// ---------------------------------------------------------------------------
__global__ __launch_bounds__(128) void reduce_kernel(
    const float* __restrict__ x, float* __restrict__ out)
{
    int b = blockIdx.x;
    int j = threadIdx.x;
    int s = d_seg_start[b];
    int e = (s < 0) ? 0 : d_seg_end[b];
    if (s < 0) s = 0;

    float sum = 0.f, mx = -CUDART_INF_F;
    float m0 = -CUDART_INF_F, dn0 = 0.f, ac0 = 0.f;
    float m1 = -CUDART_INF_F, dn1 = 0.f, ac1 = 0.f;

    int n = s;
    for (; n + 2 <= e; n += 2) {
        float xv0 = __ldg(x + (size_t)n * H + j);
        float g0  = d_gate2[n] + d_gate2[NPAD + n];
        float xv1 = __ldg(x + (size_t)(n + 1) * H + j);
        float g1  = d_gate2[n + 1] + d_gate2[NPAD + n + 1];
        sum += xv0 + xv1;
        mx = fmaxf(mx, fmaxf(xv0, xv1));
        if (g0 > m0) { float sc = __expf(m0 - g0); dn0 *= sc; ac0 *= sc; m0 = g0; }
        float e0 = __expf(g0 - m0); dn0 += e0; ac0 = fmaf(e0, xv0, ac0);
        if (g1 > m1) { float sc = __expf(m1 - g1); dn1 *= sc; ac1 *= sc; m1 = g1; }
        float e1 = __expf(g1 - m1); dn1 += e1; ac1 = fmaf(e1, xv1, ac1);
    }
    if (n < e) {
        float xv = __ldg(x + (size_t)n * H + j);
        float g  = d_gate2[n] + d_gate2[NPAD + n];
        sum += xv; mx = fmaxf(mx, xv);
        if (g > m0) { float sc = __expf(m0 - g); dn0 *= sc; ac0 *= sc; m0 = g; }
        float ev = __expf(g - m0); dn0 += ev; ac0 = fmaf(ev, xv, ac0);
    }

    int cnt = e - s;
    float denom = 0.f, acc = 0.f;
    if (cnt > 0) {
        float M  = fmaxf(m0, m1);
        float s0 = (m0 > -CUDART_INF_F) ? __expf(m0 - M) : 0.f;
        float s1 = (m1 > -CUDART_INF_F) ? __expf(m1 - M) : 0.f;
        denom = dn0 * s0 + dn1 * s1;
        acc   = ac0 * s0 + ac1 * s1;
    }
    float* o = out + (size_t)b * (3 * H);
    o[j]         = sum / fmaxf((float)cnt, 1.f);
    o[H + j]     = mx;
    o[2 * H + j] = (cnt > 0) ? (acc / denom) : 0.f;
}

// ---------------------------------------------------------------------------
extern "C" void kernel_launch(void* const* d_in, const int* in_sizes, int n_in,
                              void* d_out, int out_size) {
    const float* x  = (const float*)d_in[0];
    const float* W1 = (const float*)d_in[1];
    const float* b1 = (const float*)d_in[2];
    const float* W2 = (const float*)d_in[3];
    const int*   bi = (const int*)d_in[5];

    const int N = in_sizes[5];
    const int B = out_size / (3 * H);
    float* out = (float*)d_out;

    static int inited = 0;
    static int sms = 148;
    if (!inited) {
        cudaFuncSetAttribute(gate_mma_kernel,
                             cudaFuncAttributeMaxDynamicSharedMemorySize, SMEM_TOTAL);
        int dev = 0;
        cudaGetDevice(&dev);
        cudaDeviceGetAttribute(&sms, cudaDevAttrMultiProcessorCount, dev);
        inited = 1;
    }

    const int numTiles = (N + 63) / 64;
    const int half_grid = (2 * sms < numTiles) ? 2 * sms : numTiles;

    init_bounds_kernel<<<(B + 255) / 256, 256>>>(B);
    bounds_kernel<<<(N + 255) / 256, 256>>>(bi, N);
    prep_w1_kernel<<<(H * H + 255) / 256, 256>>>(W1);
    gate_mma_kernel<<<half_grid * 2, 256, SMEM_TOTAL>>>(x, b1, W2, N);
    reduce_kernel<<<B, H>>>(x, out);
}

// round 10
// speedup vs baseline: 1.0510x; 1.0510x over previous
#include <cuda_runtime.h>
#include <cuda_bf16.h>
#include <math_constants.h>
#include <cstdint>

#define H 128
#define NPAD 1048576
#define SEG_CAP 65536

#define RST32 528                        // fp32 stage row stride bytes (132 floats)
#define RSTB  144                        // bf16 B row stride bytes (72 elems)
#define A32_BUF 33792                    // 64 x 528

// smem layout (bytes), per CTA (x2 CTAs/SM)
#define OFF_B_HI  0                      // 128 x 144 = 18432
#define OFF_B_LO  18432
#define OFF_A32   36864                  // 2 bufs x 33792 = 67584
#define OFF_SGATE 104448                 // 128 floats = 512
#define OFF_SB1   104960                 // 256
#define OFF_SW2   105216                 // 256
#define SMEM_TOTAL 105472

__device__ float d_gate[NPAD];
__device__ int   d_seg_start[SEG_CAP];
__device__ int   d_seg_end[SEG_CAP];
__device__ __nv_bfloat16 d_W1hi[H * H];
__device__ __nv_bfloat16 d_W1lo[H * H];

// ---------------------------------------------------------------------------
__device__ __forceinline__ uint32_t smem_u32(const void* p) {
    uint32_t a;
    asm("{ .reg .u64 t; cvta.to.shared.u64 t, %1; cvt.u32.u64 %0, t; }"
        : "=r"(a) : "l"(p));
    return a;
}
__device__ __forceinline__ void ldsm_x4_t(uint32_t* r, uint32_t addr) {
    asm volatile("ldmatrix.sync.aligned.m8n8.x4.trans.shared.b16 {%0,%1,%2,%3}, [%4];"
                 : "=r"(r[0]), "=r"(r[1]), "=r"(r[2]), "=r"(r[3]) : "r"(addr));
}
__device__ __forceinline__ void mma16816(float* d, const uint32_t* a,
                                         const uint32_t* b) {
    asm volatile(
        "mma.sync.aligned.m16n8k16.row.col.f32.bf16.bf16.f32 "
        "{%0,%1,%2,%3}, {%4,%5,%6,%7}, {%8,%9}, {%0,%1,%2,%3};"
        : "+f"(d[0]), "+f"(d[1]), "+f"(d[2]), "+f"(d[3])
        : "r"(a[0]), "r"(a[1]), "r"(a[2]), "r"(a[3]), "r"(b[0]), "r"(b[1]));
}
__device__ __forceinline__ void cp_async16(uint32_t dst, const void* src, int sz) {
    asm volatile("cp.async.cg.shared.global [%0], [%1], 16, %2;"
                 :: "r"(dst), "l"(src), "r"(sz) : "memory");
}
#define CP_COMMIT() asm volatile("cp.async.commit_group;" ::: "memory")
#define CP_WAIT0()  asm volatile("cp.async.wait_group 0;" ::: "memory")
#define CP_WAIT1()  asm volatile("cp.async.wait_group 1;" ::: "memory")

__device__ __forceinline__ float2 lds_f2(uint32_t addr) {
    float2 v;
    asm volatile("ld.shared.v2.f32 {%0,%1}, [%2];"
                 : "=f"(v.x), "=f"(v.y) : "r"(addr));
    return v;
}
__device__ __forceinline__ uint32_t pack_hi(float2 v) {
    __nv_bfloat162 h = __floats2bfloat162_rn(v.x, v.y);
    return *(uint32_t*)&h;
}
__device__ __forceinline__ uint32_t pack_lo(float2 v, uint32_t hiP) {
    __nv_bfloat162 h = *(__nv_bfloat162*)&hiP;
    __nv_bfloat162 l = __floats2bfloat162_rn(v.x - __bfloat162float(h.x),
                                             v.y - __bfloat162float(h.y));
    return *(uint32_t*)&l;
}

// ---------------------------------------------------------------------------
// Segment bounds / gate zero
// ---------------------------------------------------------------------------
__global__ void init_bounds_kernel(int B) {
    int b = blockIdx.x * blockDim.x + threadIdx.x;
    if (b < B) { d_seg_start[b] = -1; d_seg_end[b] = -1; }
}
__global__ void bounds_kernel(const int* __restrict__ bi, int N) {
    int n = blockIdx.x * blockDim.x + threadIdx.x;
    if (n >= N) return;
    int b = bi[n];
    if (n == 0 || bi[n - 1] != b) d_seg_start[b] = n;
    if (n == N - 1 || bi[n + 1] != b) d_seg_end[b] = n + 1;
}
__global__ void zero_gate_kernel(int N4) {
    int i = blockIdx.x * blockDim.x + threadIdx.x;
    if (i < N4) ((float4*)d_gate)[i] = make_float4(0.f, 0.f, 0.f, 0.f);
}

// ---------------------------------------------------------------------------
// W1 -> bf16 hi/lo split (runs once)
// ---------------------------------------------------------------------------
__global__ void prep_w1_kernel(const float* __restrict__ W1) {
    int idx = blockIdx.x * blockDim.x + threadIdx.x;
    if (idx >= H * H) return;
    float v = W1[idx];
    __nv_bfloat16 hi = __float2bfloat16(v);
    __nv_bfloat16 lo = __float2bfloat16(v - __bfloat162float(hi));
    d_W1hi[idx] = hi;
    d_W1lo[idx] = lo;
}

__device__ __forceinline__ void issue_cp(const float* __restrict__ x, uint32_t sb,
                                         long t, int buf, int N, int tid) {
    long m0 = t * 64;
    uint32_t dst0 = sb + OFF_A32 + buf * A32_BUF;
#pragma unroll
    for (int c = 0; c < 8; c++) {
        int chunk = c * 256 + tid;           // 2048 chunks of 16B
        int row = chunk >> 5, col16 = chunk & 31;
        long gm = m0 + row;
        const float* src = x + (size_t)(gm < N ? gm : 0) * H + col16 * 4;
        cp_async16(dst0 + row * RST32 + col16 * 16, src, gm < N ? 16 : 0);
    }
    CP_COMMIT();
}

// ---------------------------------------------------------------------------
// Gate kernel: persistent, 2 CTAs/SM. CTA = (64-row tile, 64-col half).
// 256 thr = 8 warps (4M x 2N), warp tile 16x32. In-register A convert with
// explicit next-k prefetch; THREE accumulator banks so no accumulator is
// written twice within a k-step (kills HMMA RAW stalls).
// ---------------------------------------------------------------------------
__global__ __launch_bounds__(256, 2) void gate_mma_kernel(
    const float* __restrict__ x, const float* __restrict__ b1,
    const float* __restrict__ W2, int N)
{
    extern __shared__ char smem[];
    const uint32_t sb = smem_u32(smem);
    const int tid = threadIdx.x;
    const int wid = tid >> 5, lane = tid & 31;
    const int warp_m = wid & 3;          // rows warp_m*16
    const int warp_n = wid >> 2;         // local cols warp_n*32
    const int half = blockIdx.x & 1;
    const long tile0 = blockIdx.x >> 1;
    const long tstride = gridDim.x >> 1;

    float* sgate = (float*)(smem + OFF_SGATE);
    float* sb1   = (float*)(smem + OFF_SB1);
    float* sw2   = (float*)(smem + OFF_SW2);
    if (tid < 64) {
        sb1[tid] = b1[half * 64 + tid];
        sw2[tid] = W2[half * 64 + tid];
    }

    const int numTiles = (N + 63) / 64;

    if (tile0 < numTiles) issue_cp(x, sb, tile0, 0, N, tid);

    // B half (W1 hi/lo) -> smem once
#pragma unroll
    for (int c = 0; c < 4; c++) {
        int idx = c * 256 + tid;             // 1024 uint4 per matrix
        int k = idx >> 3, n8 = (idx & 7) << 3;
        uint32_t off = (uint32_t)k * RSTB + (uint32_t)n8 * 2;
        *(uint4*)(smem + OFF_B_HI + off) = *(const uint4*)(d_W1hi + k * H + half * 64 + n8);
        *(uint4*)(smem + OFF_B_LO + off) = *(const uint4*)(d_W1lo + k * H + half * 64 + n8);
    }

    if (tile0 + tstride < numTiles) issue_cp(x, sb, tile0 + tstride, 1, N, tid);

    // per-lane addresses
    const int fr = lane >> 2;            // 0..7
    const int fc = (lane & 3) * 2;       // 0,2,4,6
    const uint32_t a_base = sb + OFF_A32
                          + (uint32_t)(warp_m * 16 + fr) * RST32 + (uint32_t)fc * 4;
    const uint32_t b_base = sb + (uint32_t)(lane & 15) * RSTB
                          + (uint32_t)(warp_n * 32 + (lane >> 4) * 8) * 2;

    int buf = 0;
    for (long t = tile0; t < numTiles; t += tstride, buf ^= 1) {
        const bool hn  = (t + tstride)     < numTiles;
        const bool hnn = (t + 2 * tstride) < numTiles;

        if (hn) { CP_WAIT1(); } else { CP_WAIT0(); }
        __syncthreads();                 // A32[buf] visible; sgate free

        float accH[4][4], accL1[4][4], accL2[4][4];
#pragma unroll
        for (int ni = 0; ni < 4; ni++)
#pragma unroll
            for (int r = 0; r < 4; r++) {
                accH[ni][r] = 0.f; accL1[ni][r] = 0.f; accL2[ni][r] = 0.f;
            }

        const uint32_t aK = a_base + (uint32_t)buf * A32_BUF;

        // k=0 A floats
        float2 f0 = lds_f2(aK);
        float2 f1 = lds_f2(aK + 8 * RST32);
        float2 f2 = lds_f2(aK + 32);
        float2 f3 = lds_f2(aK + 8 * RST32 + 32);

#pragma unroll
        for (int k = 0; k < 8; k++) {
            uint32_t ah[4], al[4];
            ah[0] = pack_hi(f0); al[0] = pack_lo(f0, ah[0]);
            ah[1] = pack_hi(f1); al[1] = pack_lo(f1, ah[1]);
            ah[2] = pack_hi(f2); al[2] = pack_lo(f2, ah[2]);
            ah[3] = pack_hi(f3); al[3] = pack_lo(f3, ah[3]);

            // prefetch next k-step's A floats (overlaps MMAs below)
            if (k < 7) {
                const uint32_t an = aK + (uint32_t)(k + 1) * 64;
                f0 = lds_f2(an);
                f1 = lds_f2(an + 8 * RST32);
                f2 = lds_f2(an + 32);
                f3 = lds_f2(an + 8 * RST32 + 32);
            }

#pragma unroll
            for (int nb = 0; nb < 2; nb++) {
                uint32_t bh[4], bl[4];
                uint32_t bo = b_base + (uint32_t)k * 16 * RSTB + nb * 32;
                ldsm_x4_t(bh, bo + OFF_B_HI);
                ldsm_x4_t(bl, bo + OFF_B_LO);
                mma16816(accH[nb * 2],      ah, &bh[0]);
                mma16816(accH[nb * 2 + 1],  ah, &bh[2]);
                mma16816(accL1[nb * 2],     al, &bh[0]);
                mma16816(accL1[nb * 2 + 1], al, &bh[2]);
                mma16816(accL2[nb * 2],     ah, &bl[0]);
                mma16816(accL2[nb * 2 + 1], ah, &bl[2]);
            }
        }

        // ---- epilogue: silu + dot(W2 slice), warp row-reduce ----
        float part[2] = {0.f, 0.f};
#pragma unroll
        for (int ni = 0; ni < 4; ni++)
#pragma unroll
            for (int r = 0; r < 4; r++) {
                int col = warp_n * 32 + ni * 8 + (lane & 3) * 2 + (r & 1);
                float vv = accH[ni][r] + accL1[ni][r] + accL2[ni][r] + sb1[col];
                float sl = vv / (1.f + __expf(-vv));
                part[r >> 1] = fmaf(sl, sw2[col], part[r >> 1]);
            }
#pragma unroll
        for (int hh = 0; hh < 2; hh++) {
            float p = part[hh];
            p += __shfl_xor_sync(0xFFFFFFFF, p, 1);
            p += __shfl_xor_sync(0xFFFFFFFF, p, 2);
            part[hh] = p;
        }
        if ((lane & 3) == 0) {
#pragma unroll
            for (int hh = 0; hh < 2; hh++) {
                int row = warp_m * 16 + hh * 8 + (lane >> 2);
                sgate[warp_n * 64 + row] = part[hh];
            }
        }
        __syncthreads();                 // A32[buf] reads done; sgate complete

        if (hnn) issue_cp(x, sb, t + 2 * tstride, buf, N, tid);

        // two halves atomically add into one gate array (order-commutative)
        if (tid < 64) {
            long gm = t * 64 + tid;
            if (gm < N)
                atomicAdd(&d_gate[gm], sgate[tid] + sgate[64 + tid]);
        }
    }
}

// ---------------------------------------------------------------------------
// Reduce kernel: per-segment mean/max/attention (b2 cancels in softmax)
// ---------------------------------------------------------------------------
__global__ __launch_bounds__(128) void reduce_kernel(
    const float* __restrict__ x, float* __restrict__ out)
{
    int b = blockIdx.x;
    int j = threadIdx.x;
    int s = d_seg_start[b];
    int e = (s < 0) ? 0 : d_seg_end[b];
    if (s < 0) s = 0;

    float sum = 0.f, mx = -CUDART_INF_F;
    float m0 = -CUDART_INF_F, dn0 = 0.f, ac0 = 0.f;
    float m1 = -CUDART_INF_F, dn1 = 0.f, ac1 = 0.f;

    int n = s;
    for (; n + 2 <= e; n += 2) {
        float xv0 = __ldg(x + (size_t)n * H + j);
        float g0  = d_gate[n];
        float xv1 = __ldg(x + (size_t)(n + 1) * H + j);
        float g1  = d_gate[n + 1];
        sum += xv0 + xv1;
        mx = fmaxf(mx, fmaxf(xv0, xv1));
        if (g0 > m0) { float sc = __expf(m0 - g0); dn0 *= sc; ac0 *= sc; m0 = g0; }
        float e0 = __expf(g0 - m0); dn0 += e0; ac0 = fmaf(e0, xv0, ac0);
        if (g1 > m1) { float sc = __expf(m1 - g1); dn1 *= sc; ac1 *= sc; m1 = g1; }
        float e1 = __expf(g1 - m1); dn1 += e1; ac1 = fmaf(e1, xv1, ac1);
    }
    if (n < e) {
        float xv = __ldg(x + (size_t)n * H + j);
        float g  = d_gate[n];
        sum += xv; mx = fmaxf(mx, xv);
        if (g > m0) { float sc = __expf(m0 - g); dn0 *= sc; ac0 *= sc; m0 = g; }
        float ev = __expf(g - m0); dn0 += ev; ac0 = fmaf(ev, xv, ac0);
    }

    int cnt = e - s;
    float denom = 0.f, acc = 0.f;
    if (cnt > 0) {
        float M  = fmaxf(m0, m1);
        float s0 = (m0 > -CUDART_INF_F) ? __expf(m0 - M) : 0.f;
        float s1 = (m1 > -CUDART_INF_F) ? __expf(m1 - M) : 0.f;
        denom = dn0 * s0 + dn1 * s1;
        acc   = ac0 * s0 + ac1 * s1;
    }
    float* o = out + (size_t)b * (3 * H);
    o[j]         = sum / fmaxf((float)cnt, 1.f);
    o[H + j]     = mx;
    o[2 * H + j] = (cnt > 0) ? (acc / denom) : 0.f;
}

// ---------------------------------------------------------------------------
extern "C" void kernel_launch(void* const* d_in, const int* in_sizes, int n_in,
                              void* d_out, int out_size) {
    const float* x  = (const float*)d_in[0];
    const float* W1 = (const float*)d_in[1];
    const float* b1 = (const float*)d_in[2];
    const float* W2 = (const float*)d_in[3];
    const int*   bi = (const int*)d_in[5];

    const int N = in_sizes[5];
    const int B = out_size / (3 * H);
    float* out = (float*)d_out;

    static int inited = 0;
    static int sms = 148;
    if (!inited) {
        cudaFuncSetAttribute(gate_mma_kernel,
                             cudaFuncAttributeMaxDynamicSharedMemorySize, SMEM_TOTAL);
        int dev = 0;
        cudaGetDevice(&dev);
        cudaDeviceGetAttribute(&sms, cudaDevAttrMultiProcessorCount, dev);
        inited = 1;
    }

    const int numTiles = (N + 63) / 64;
    const int half_grid = (2 * sms < numTiles) ? 2 * sms : numTiles;
    const int N4 = (N + 3) / 4;

    init_bounds_kernel<<<(B + 255) / 256, 256>>>(B);
    bounds_kernel<<<(N + 255) / 256, 256>>>(bi, N);
    prep_w1_kernel<<<(H * H + 255) / 256, 256>>>(W1);
    zero_gate_kernel<<<(N4 + 255) / 256, 256>>>(N4);
    gate_mma_kernel<<<half_grid * 2, 256, SMEM_TOTAL>>>(x, b1, W2, N);
    reduce_kernel<<<B, H>>>(x, out);
}

// round 11
// speedup vs baseline: 1.1242x; 1.0697x over previous
#include <cuda_runtime.h>
#include <cuda_fp16.h>
#include <math_constants.h>
#include <cstdint>

#define H 128
#define NPAD 1048576
#define SEG_CAP 65536

#define RST32 528                        // fp32 stage row stride bytes (132 floats)
#define RSTB  144                        // fp16 B row stride bytes (72 elems)
#define A32_BUF 33792                    // 64 x 528

// smem layout (bytes), per CTA (x2 CTAs/SM)
#define OFF_B_HI  0                      // 128 x 144 = 18432
#define OFF_B_LO  18432
#define OFF_A32   36864                  // 2 bufs x 33792 = 67584
#define OFF_SGATE 104448                 // 128 floats = 512
#define OFF_SB1   104960                 // 256
#define OFF_SW2   105216                 // 256
#define SMEM_TOTAL 105472

__device__ float d_gate[NPAD];
__device__ int   d_seg_start[SEG_CAP];
__device__ int   d_seg_end[SEG_CAP];
__device__ __half d_W1hi[H * H];
__device__ __half d_W1lo[H * H];

// ---------------------------------------------------------------------------
__device__ __forceinline__ uint32_t smem_u32(const void* p) {
    uint32_t a;
    asm("{ .reg .u64 t; cvta.to.shared.u64 t, %1; cvt.u32.u64 %0, t; }"
        : "=r"(a) : "l"(p));
    return a;
}
__device__ __forceinline__ void ldsm_x4_t(uint32_t* r, uint32_t addr) {
    asm volatile("ldmatrix.sync.aligned.m8n8.x4.trans.shared.b16 {%0,%1,%2,%3}, [%4];"
                 : "=r"(r[0]), "=r"(r[1]), "=r"(r[2]), "=r"(r[3]) : "r"(addr));
}
__device__ __forceinline__ void mma16816h(float* d, const uint32_t* a,
                                          const uint32_t* b) {
    asm volatile(
        "mma.sync.aligned.m16n8k16.row.col.f32.f16.f16.f32 "
        "{%0,%1,%2,%3}, {%4,%5,%6,%7}, {%8,%9}, {%0,%1,%2,%3};"
        : "+f"(d[0]), "+f"(d[1]), "+f"(d[2]), "+f"(d[3])
        : "r"(a[0]), "r"(a[1]), "r"(a[2]), "r"(a[3]), "r"(b[0]), "r"(b[1]));
}
__device__ __forceinline__ void cp_async16(uint32_t dst, const void* src, int sz) {
    asm volatile("cp.async.cg.shared.global [%0], [%1], 16, %2;"
                 :: "r"(dst), "l"(src), "r"(sz) : "memory");
}
#define CP_COMMIT() asm volatile("cp.async.commit_group;" ::: "memory")
#define CP_WAIT0()  asm volatile("cp.async.wait_group 0;" ::: "memory")
#define CP_WAIT1()  asm volatile("cp.async.wait_group 1;" ::: "memory")

__device__ __forceinline__ float2 lds_f2(uint32_t addr) {
    float2 v;
    asm volatile("ld.shared.v2.f32 {%0,%1}, [%2];"
                 : "=f"(v.x), "=f"(v.y) : "r"(addr));
    return v;
}
__device__ __forceinline__ uint32_t pack_h2(float2 v) {
    __half2 h = __floats2half2_rn(v.x, v.y);
    return *(uint32_t*)&h;
}

// ---------------------------------------------------------------------------
// Segment bounds / gate zero
// ---------------------------------------------------------------------------
__global__ void init_bounds_kernel(int B) {
    int b = blockIdx.x * blockDim.x + threadIdx.x;
    if (b < B) { d_seg_start[b] = -1; d_seg_end[b] = -1; }
}
__global__ void bounds_kernel(const int* __restrict__ bi, int N) {
    int n = blockIdx.x * blockDim.x + threadIdx.x;
    if (n >= N) return;
    int b = bi[n];
    if (n == 0 || bi[n - 1] != b) d_seg_start[b] = n;
    if (n == N - 1 || bi[n + 1] != b) d_seg_end[b] = n + 1;
}
__global__ void zero_gate_kernel(int N4) {
    int i = blockIdx.x * blockDim.x + threadIdx.x;
    if (i < N4) ((float4*)d_gate)[i] = make_float4(0.f, 0.f, 0.f, 0.f);
}

// ---------------------------------------------------------------------------
// W1 -> fp16 hi/lo split (runs once)
// ---------------------------------------------------------------------------
__global__ void prep_w1_kernel(const float* __restrict__ W1) {
    int idx = blockIdx.x * blockDim.x + threadIdx.x;
    if (idx >= H * H) return;
    float v = W1[idx];
    __half hi = __float2half_rn(v);
    __half lo = __float2half_rn(v - __half2float(hi));
    d_W1hi[idx] = hi;
    d_W1lo[idx] = lo;
}

__device__ __forceinline__ void issue_cp(const float* __restrict__ x, uint32_t sb,
                                         long t, int buf, int N, int tid) {
    long m0 = t * 64;
    uint32_t dst0 = sb + OFF_A32 + buf * A32_BUF;
#pragma unroll
    for (int c = 0; c < 8; c++) {
        int chunk = c * 256 + tid;           // 2048 chunks of 16B
        int row = chunk >> 5, col16 = chunk & 31;
        long gm = m0 + row;
        const float* src = x + (size_t)(gm < N ? gm : 0) * H + col16 * 4;
        cp_async16(dst0 + row * RST32 + col16 * 16, src, gm < N ? 16 : 0);
    }
    CP_COMMIT();
}

// ---------------------------------------------------------------------------
// Gate kernel: persistent, 2 CTAs/SM. CTA = (64-row tile, 64-col half).
// 256 thr = 8 warps (4M x 2N), warp tile 16x32.
// fp16 2-product: A = fp16(x) (single rounding, in-register convert);
// B = W1 split into fp16 hi + fp16 lo in smem. acc = A*Bhi + A*Blo in two
// banks. A-float and B-fragment prefetch (k+1) hide LDS/ldsm latency.
// ---------------------------------------------------------------------------
__global__ __launch_bounds__(256, 2) void gate_mma_kernel(
    const float* __restrict__ x, const float* __restrict__ b1,
    const float* __restrict__ W2, int N)
{
    extern __shared__ char smem[];
    const uint32_t sb = smem_u32(smem);
    const int tid = threadIdx.x;
    const int wid = tid >> 5, lane = tid & 31;
    const int warp_m = wid & 3;          // rows warp_m*16
    const int warp_n = wid >> 2;         // local cols warp_n*32
    const int half = blockIdx.x & 1;
    const long tile0 = blockIdx.x >> 1;
    const long tstride = gridDim.x >> 1;

    float* sgate = (float*)(smem + OFF_SGATE);
    float* sb1   = (float*)(smem + OFF_SB1);
    float* sw2   = (float*)(smem + OFF_SW2);
    if (tid < 64) {
        sb1[tid] = b1[half * 64 + tid];
        sw2[tid] = W2[half * 64 + tid];
    }

    const int numTiles = (N + 63) / 64;

    if (tile0 < numTiles) issue_cp(x, sb, tile0, 0, N, tid);

    // B half (W1 fp16 hi/lo) -> smem once
#pragma unroll
    for (int c = 0; c < 4; c++) {
        int idx = c * 256 + tid;             // 1024 uint4 per matrix
        int k = idx >> 3, n8 = (idx & 7) << 3;
        uint32_t off = (uint32_t)k * RSTB + (uint32_t)n8 * 2;
        *(uint4*)(smem + OFF_B_HI + off) = *(const uint4*)(d_W1hi + k * H + half * 64 + n8);
        *(uint4*)(smem + OFF_B_LO + off) = *(const uint4*)(d_W1lo + k * H + half * 64 + n8);
    }

    if (tile0 + tstride < numTiles) issue_cp(x, sb, tile0 + tstride, 1, N, tid);

    // per-lane addresses
    const int fr = lane >> 2;            // 0..7
    const int fc = (lane & 3) * 2;       // 0,2,4,6
    const uint32_t a_base = sb + OFF_A32
                          + (uint32_t)(warp_m * 16 + fr) * RST32 + (uint32_t)fc * 4;
    const uint32_t b_base = sb + (uint32_t)(lane & 15) * RSTB
                          + (uint32_t)(warp_n * 32 + (lane >> 4) * 8) * 2;

    int buf = 0;
    for (long t = tile0; t < numTiles; t += tstride, buf ^= 1) {
        const bool hn  = (t + tstride)     < numTiles;
        const bool hnn = (t + 2 * tstride) < numTiles;

        if (hn) { CP_WAIT1(); } else { CP_WAIT0(); }
        __syncthreads();                 // A32[buf] visible; sgate free

        float accH[4][4], accL[4][4];
#pragma unroll
        for (int ni = 0; ni < 4; ni++)
#pragma unroll
            for (int r = 0; r < 4; r++) { accH[ni][r] = 0.f; accL[ni][r] = 0.f; }

        const uint32_t aK = a_base + (uint32_t)buf * A32_BUF;

        // k=0 A floats + B fragments
        float2 f0 = lds_f2(aK);
        float2 f1 = lds_f2(aK + 8 * RST32);
        float2 f2 = lds_f2(aK + 32);
        float2 f3 = lds_f2(aK + 8 * RST32 + 32);
        uint32_t bh[2][2][4], bl[2][2][4];   // [pingpong][nb][frag]
#pragma unroll
        for (int nb = 0; nb < 2; nb++) {
            uint32_t bo = b_base + nb * 32;
            ldsm_x4_t(bh[0][nb], bo + OFF_B_HI);
            ldsm_x4_t(bl[0][nb], bo + OFF_B_LO);
        }

#pragma unroll
        for (int k = 0; k < 8; k++) {
            const int cur = k & 1, nxt = cur ^ 1;
            // convert A (single fp16 rounding)
            uint32_t ah[4];
            ah[0] = pack_h2(f0);
            ah[1] = pack_h2(f1);
            ah[2] = pack_h2(f2);
            ah[3] = pack_h2(f3);

            // prefetch next k-step (A floats + B fragments)
            if (k < 7) {
                const uint32_t an = aK + (uint32_t)(k + 1) * 64;
                f0 = lds_f2(an);
                f1 = lds_f2(an + 8 * RST32);
                f2 = lds_f2(an + 32);
                f3 = lds_f2(an + 8 * RST32 + 32);
                const uint32_t bn = b_base + (uint32_t)(k + 1) * 16 * RSTB;
#pragma unroll
                for (int nb = 0; nb < 2; nb++) {
                    uint32_t bo = bn + nb * 32;
                    ldsm_x4_t(bh[nxt][nb], bo + OFF_B_HI);
                    ldsm_x4_t(bl[nxt][nb], bo + OFF_B_LO);
                }
            }

            // 8 HMMA, each accumulator written once per k-step
#pragma unroll
            for (int nb = 0; nb < 2; nb++) {
                mma16816h(accH[nb * 2],     ah, &bh[cur][nb][0]);
                mma16816h(accH[nb * 2 + 1], ah, &bh[cur][nb][2]);
                mma16816h(accL[nb * 2],     ah, &bl[cur][nb][0]);
                mma16816h(accL[nb * 2 + 1], ah, &bl[cur][nb][2]);
            }
        }

        // ---- epilogue: silu + dot(W2 slice), warp row-reduce ----
        float part[2] = {0.f, 0.f};
#pragma unroll
        for (int ni = 0; ni < 4; ni++)
#pragma unroll
            for (int r = 0; r < 4; r++) {
                int col = warp_n * 32 + ni * 8 + (lane & 3) * 2 + (r & 1);
                float vv = accH[ni][r] + accL[ni][r] + sb1[col];
                float sl = vv / (1.f + __expf(-vv));
                part[r >> 1] = fmaf(sl, sw2[col], part[r >> 1]);
            }
#pragma unroll
        for (int hh = 0; hh < 2; hh++) {
            float p = part[hh];
            p += __shfl_xor_sync(0xFFFFFFFF, p, 1);
            p += __shfl_xor_sync(0xFFFFFFFF, p, 2);
            part[hh] = p;
        }
        if ((lane & 3) == 0) {
#pragma unroll
            for (int hh = 0; hh < 2; hh++) {
                int row = warp_m * 16 + hh * 8 + (lane >> 2);
                sgate[warp_n * 64 + row] = part[hh];
            }
        }
        __syncthreads();                 // A32[buf] reads done; sgate complete

        if (hnn) issue_cp(x, sb, t + 2 * tstride, buf, N, tid);

        // two halves atomically add into one gate array (order-commutative)
        if (tid < 64) {
            long gm = t * 64 + tid;
            if (gm < N)
                atomicAdd(&d_gate[gm], sgate[tid] + sgate[64 + tid]);
        }
    }
}

// ---------------------------------------------------------------------------
// Reduce kernel: per-segment mean/max/attention (b2 cancels in softmax)
// ---------------------------------------------------------------------------
__global__ __launch_bounds__(128) void reduce_kernel(
    const float* __restrict__ x, float* __restrict__ out)
{
    int b = blockIdx.x;
    int j = threadIdx.x;
    int s = d_seg_start[b];
    int e = (s < 0) ? 0 : d_seg_end[b];
    if (s < 0) s = 0;

    float sum = 0.f, mx = -CUDART_INF_F;
    float m0 = -CUDART_INF_F, dn0 = 0.f, ac0 = 0.f;
    float m1 = -CUDART_INF_F, dn1 = 0.f, ac1 = 0.f;

    int n = s;
    for (; n + 2 <= e; n += 2) {
        float xv0 = __ldg(x + (size_t)n * H + j);
        float g0  = d_gate[n];
        float xv1 = __ldg(x + (size_t)(n + 1) * H + j);
        float g1  = d_gate[n + 1];
        sum += xv0 + xv1;
        mx = fmaxf(mx, fmaxf(xv0, xv1));
        if (g0 > m0) { float sc = __expf(m0 - g0); dn0 *= sc; ac0 *= sc; m0 = g0; }
        float e0 = __expf(g0 - m0); dn0 += e0; ac0 = fmaf(e0, xv0, ac0);
        if (g1 > m1) { float sc = __expf(m1 - g1); dn1 *= sc; ac1 *= sc; m1 = g1; }
        float e1 = __expf(g1 - m1); dn1 += e1; ac1 = fmaf(e1, xv1, ac1);
    }
    if (n < e) {
        float xv = __ldg(x + (size_t)n * H + j);
        float g  = d_gate[n];
        sum += xv; mx = fmaxf(mx, xv);
        if (g > m0) { float sc = __expf(m0 - g); dn0 *= sc; ac0 *= sc; m0 = g; }
        float ev = __expf(g - m0); dn0 += ev; ac0 = fmaf(ev, xv, ac0);
    }

    int cnt = e - s;
    float denom = 0.f, acc = 0.f;
    if (cnt > 0) {
        float M  = fmaxf(m0, m1);
        float s0 = (m0 > -CUDART_INF_F) ? __expf(m0 - M) : 0.f;
        float s1 = (m1 > -CUDART_INF_F) ? __expf(m1 - M) : 0.f;
        denom = dn0 * s0 + dn1 * s1;
        acc   = ac0 * s0 + ac1 * s1;
    }
    float* o = out + (size_t)b * (3 * H);
    o[j]         = sum / fmaxf((float)cnt, 1.f);
    o[H + j]     = mx;
    o[2 * H + j] = (cnt > 0) ? (acc / denom) : 0.f;
}

// ---------------------------------------------------------------------------
extern "C" void kernel_launch(void* const* d_in, const int* in_sizes, int n_in,
                              void* d_out, int out_size) {
    const float* x  = (const float*)d_in[0];
    const float* W1 = (const float*)d_in[1];
    const float* b1 = (const float*)d_in[2];
    const float* W2 = (const float*)d_in[3];
    const int*   bi = (const int*)d_in[5];

    const int N = in_sizes[5];
    const int B = out_size / (3 * H);
    float* out = (float*)d_out;

    static int inited = 0;
    static int sms = 148;
    if (!inited) {
        cudaFuncSetAttribute(gate_mma_kernel,
                             cudaFuncAttributeMaxDynamicSharedMemorySize, SMEM_TOTAL);
        int dev = 0;
        cudaGetDevice(&dev);
        cudaDeviceGetAttribute(&sms, cudaDevAttrMultiProcessorCount, dev);
        inited = 1;
    }

    const int numTiles = (N + 63) / 64;
    const int half_grid = (2 * sms < numTiles) ? 2 * sms : numTiles;
    const int N4 = (N + 3) / 4;

    init_bounds_kernel<<<(B + 255) / 256, 256>>>(B);
    bounds_kernel<<<(N + 255) / 256, 256>>>(bi, N);
    prep_w1_kernel<<<(H * H + 255) / 256, 256>>>(W1);
    zero_gate_kernel<<<(N4 + 255) / 256, 256>>>(N4);
    gate_mma_kernel<<<half_grid * 2, 256, SMEM_TOTAL>>>(x, b1, W2, N);
    reduce_kernel<<<B, H>>>(x, out);
}

// round 12
// speedup vs baseline: 1.4768x; 1.3136x over previous
#include <cuda_runtime.h>
#include <cuda_fp16.h>
#include <math_constants.h>
#include <cstdint>

#define H 128
#define NPAD 1048576
#define SEG_CAP 65536

#define RST32 528                        // fp32 stage row stride bytes (132 floats)
#define RSTB  272                        // fp16 B row stride bytes (136 elems)
#define A32_BUF 33792                    // 64 x 528

// smem layout (bytes), per CTA (x2 CTAs/SM)
#define OFF_B     0                      // 128 x 272 = 34816
#define OFF_A32   34816                  // 2 bufs x 33792 = 67584
#define OFF_SGATE 102400                 // 2 x 64 floats = 512
#define OFF_SB1   102912                 // 512
#define OFF_SW2   103424                 // 512
#define SMEM_TOTAL 103936

__device__ float d_gate[NPAD];
__device__ int   d_seg_start[SEG_CAP];
__device__ int   d_seg_end[SEG_CAP];
__device__ __half d_W1h[H * H];

// ---------------------------------------------------------------------------
__device__ __forceinline__ uint32_t smem_u32(const void* p) {
    uint32_t a;
    asm("{ .reg .u64 t; cvta.to.shared.u64 t, %1; cvt.u32.u64 %0, t; }"
        : "=r"(a) : "l"(p));
    return a;
}
__device__ __forceinline__ void ldsm_x4_t(uint32_t* r, uint32_t addr) {
    asm volatile("ldmatrix.sync.aligned.m8n8.x4.trans.shared.b16 {%0,%1,%2,%3}, [%4];"
                 : "=r"(r[0]), "=r"(r[1]), "=r"(r[2]), "=r"(r[3]) : "r"(addr));
}
__device__ __forceinline__ void mma16816h(float* d, const uint32_t* a,
                                          const uint32_t* b) {
    asm volatile(
        "mma.sync.aligned.m16n8k16.row.col.f32.f16.f16.f32 "
        "{%0,%1,%2,%3}, {%4,%5,%6,%7}, {%8,%9}, {%0,%1,%2,%3};"
        : "+f"(d[0]), "+f"(d[1]), "+f"(d[2]), "+f"(d[3])
        : "r"(a[0]), "r"(a[1]), "r"(a[2]), "r"(a[3]), "r"(b[0]), "r"(b[1]));
}
__device__ __forceinline__ void cp_async16(uint32_t dst, const void* src, int sz) {
    asm volatile("cp.async.cg.shared.global [%0], [%1], 16, %2;"
                 :: "r"(dst), "l"(src), "r"(sz) : "memory");
}
#define CP_COMMIT() asm volatile("cp.async.commit_group;" ::: "memory")
#define CP_WAIT0()  asm volatile("cp.async.wait_group 0;" ::: "memory")
#define CP_WAIT1()  asm volatile("cp.async.wait_group 1;" ::: "memory")

__device__ __forceinline__ float2 lds_f2(uint32_t addr) {
    float2 v;
    asm volatile("ld.shared.v2.f32 {%0,%1}, [%2];"
                 : "=f"(v.x), "=f"(v.y) : "r"(addr));
    return v;
}
__device__ __forceinline__ uint32_t pack_h2(float2 v) {
    __half2 h = __floats2half2_rn(v.x, v.y);
    return *(uint32_t*)&h;
}

// ---------------------------------------------------------------------------
// Segment bounds
// ---------------------------------------------------------------------------
__global__ void init_bounds_kernel(int B) {
    int b = blockIdx.x * blockDim.x + threadIdx.x;
    if (b < B) { d_seg_start[b] = -1; d_seg_end[b] = -1; }
}
__global__ void bounds_kernel(const int* __restrict__ bi, int N) {
    int n = blockIdx.x * blockDim.x + threadIdx.x;
    if (n >= N) return;
    int b = bi[n];
    if (n == 0 || bi[n - 1] != b) d_seg_start[b] = n;
    if (n == N - 1 || bi[n + 1] != b) d_seg_end[b] = n + 1;
}

// ---------------------------------------------------------------------------
// W1 -> fp16 (runs once)
// ---------------------------------------------------------------------------
__global__ void prep_w1_kernel(const float* __restrict__ W1) {
    int idx = blockIdx.x * blockDim.x + threadIdx.x;
    if (idx >= H * H) return;
    d_W1h[idx] = __float2half_rn(W1[idx]);
}

__device__ __forceinline__ void issue_cp(const float* __restrict__ x, uint32_t sb,
                                         long t, int buf, int N, int tid) {
    long m0 = t * 64;
    uint32_t dst0 = sb + OFF_A32 + buf * A32_BUF;
#pragma unroll
    for (int c = 0; c < 8; c++) {
        int chunk = c * 256 + tid;           // 2048 chunks of 16B
        int row = chunk >> 5, col16 = chunk & 31;
        long gm = m0 + row;
        const float* src = x + (size_t)(gm < N ? gm : 0) * H + col16 * 4;
        cp_async16(dst0 + row * RST32 + col16 * 16, src, gm < N ? 16 : 0);
    }
    CP_COMMIT();
}

// ---------------------------------------------------------------------------
// Gate kernel: persistent, 2 CTAs/SM. CTA = full 64x128 tile, single fp16
// product (gate = fp16(x) @ fp16(W1)). 256 thr = 8 warps (4M x 2N), warp
// tile 16x64 (acc 32 regs). A floats + B fragments prefetched one k ahead.
// ---------------------------------------------------------------------------
__global__ __launch_bounds__(256, 2) void gate_mma_kernel(
    const float* __restrict__ x, const float* __restrict__ b1,
    const float* __restrict__ W2, int N)
{
    extern __shared__ char smem[];
    const uint32_t sb = smem_u32(smem);
    const int tid = threadIdx.x;
    const int wid = tid >> 5, lane = tid & 31;
    const int warp_m = wid & 3;          // rows warp_m*16
    const int warp_n = wid >> 2;         // cols warp_n*64
    const long tile0 = blockIdx.x;
    const long tstride = gridDim.x;

    float* sgate = (float*)(smem + OFF_SGATE);
    float* sb1   = (float*)(smem + OFF_SB1);
    float* sw2   = (float*)(smem + OFF_SW2);
    if (tid < H) { sb1[tid] = b1[tid]; sw2[tid] = W2[tid]; }

    const int numTiles = (N + 63) / 64;

    if (tile0 < numTiles) issue_cp(x, sb, tile0, 0, N, tid);

    // B (W1 fp16) -> smem once: 2048 uint4
#pragma unroll
    for (int c = 0; c < 8; c++) {
        int idx = c * 256 + tid;
        int k = idx >> 4, n8 = (idx & 15) << 3;
        uint32_t off = (uint32_t)k * RSTB + (uint32_t)n8 * 2;
        *(uint4*)(smem + OFF_B + off) = *(const uint4*)(d_W1h + k * H + n8);
    }

    if (tile0 + tstride < numTiles) issue_cp(x, sb, tile0 + tstride, 1, N, tid);

    // per-lane addresses
    const int fr = lane >> 2;            // 0..7
    const int fc = (lane & 3) * 2;       // 0,2,4,6
    const uint32_t a_base = sb + OFF_A32
                          + (uint32_t)(warp_m * 16 + fr) * RST32 + (uint32_t)fc * 4;
    const uint32_t b_base = sb + OFF_B + (uint32_t)(lane & 15) * RSTB
                          + (uint32_t)(warp_n * 64 + (lane >> 4) * 8) * 2;

    int buf = 0;
    for (long t = tile0; t < numTiles; t += tstride, buf ^= 1) {
        const bool hn  = (t + tstride)     < numTiles;
        const bool hnn = (t + 2 * tstride) < numTiles;

        if (hn) { CP_WAIT1(); } else { CP_WAIT0(); }
        __syncthreads();                 // A32[buf] visible; sgate free

        float acc[8][4];
#pragma unroll
        for (int ni = 0; ni < 8; ni++)
#pragma unroll
            for (int r = 0; r < 4; r++) acc[ni][r] = 0.f;

        const uint32_t aK = a_base + (uint32_t)buf * A32_BUF;

        // k=0 A floats + B fragments
        float2 f0 = lds_f2(aK);
        float2 f1 = lds_f2(aK + 8 * RST32);
        float2 f2 = lds_f2(aK + 32);
        float2 f3 = lds_f2(aK + 8 * RST32 + 32);
        uint32_t bfr[2][4][4];           // [pingpong][nb][frag]
#pragma unroll
        for (int nb = 0; nb < 4; nb++)
            ldsm_x4_t(bfr[0][nb], b_base + nb * 32);

#pragma unroll
        for (int k = 0; k < 8; k++) {
            const int cur = k & 1, nxt = cur ^ 1;
            uint32_t ah[4];
            ah[0] = pack_h2(f0);
            ah[1] = pack_h2(f1);
            ah[2] = pack_h2(f2);
            ah[3] = pack_h2(f3);

            if (k < 7) {
                const uint32_t an = aK + (uint32_t)(k + 1) * 64;
                f0 = lds_f2(an);
                f1 = lds_f2(an + 8 * RST32);
                f2 = lds_f2(an + 32);
                f3 = lds_f2(an + 8 * RST32 + 32);
                const uint32_t bn = b_base + (uint32_t)(k + 1) * 16 * RSTB;
#pragma unroll
                for (int nb = 0; nb < 4; nb++)
                    ldsm_x4_t(bfr[nxt][nb], bn + nb * 32);
            }

            // 8 HMMA, each accumulator written once per k-step
#pragma unroll
            for (int nb = 0; nb < 4; nb++) {
                mma16816h(acc[nb * 2],     ah, &bfr[cur][nb][0]);
                mma16816h(acc[nb * 2 + 1], ah, &bfr[cur][nb][2]);
            }
        }

        // ---- epilogue: silu + dot(W2), warp row-reduce ----
        float part[2] = {0.f, 0.f};
#pragma unroll
        for (int ni = 0; ni < 8; ni++)
#pragma unroll
            for (int r = 0; r < 4; r++) {
                int col = warp_n * 64 + ni * 8 + (lane & 3) * 2 + (r & 1);
                float vv = acc[ni][r] + sb1[col];
                float sl = vv / (1.f + __expf(-vv));
                part[r >> 1] = fmaf(sl, sw2[col], part[r >> 1]);
            }
#pragma unroll
        for (int hh = 0; hh < 2; hh++) {
            float p = part[hh];
            p += __shfl_xor_sync(0xFFFFFFFF, p, 1);
            p += __shfl_xor_sync(0xFFFFFFFF, p, 2);
            part[hh] = p;
        }
        if ((lane & 3) == 0) {
#pragma unroll
            for (int hh = 0; hh < 2; hh++) {
                int row = warp_m * 16 + hh * 8 + (lane >> 2);
                sgate[warp_n * 64 + row] = part[hh];
            }
        }
        __syncthreads();                 // A32[buf] reads done; sgate complete

        if (hnn) issue_cp(x, sb, t + 2 * tstride, buf, N, tid);

        if (tid < 64) {
            long gm = t * 64 + tid;
            if (gm < N)
                d_gate[gm] = sgate[tid] + sgate[64 + tid];
        }
    }
}

// ---------------------------------------------------------------------------
// Reduce kernel: per-segment mean/max/attention (b2 cancels in softmax)
// ---------------------------------------------------------------------------
__global__ __launch_bounds__(128) void reduce_kernel(
    const float* __restrict__ x, float* __restrict__ out)
{
    int b = blockIdx.x;
    int j = threadIdx.x;
    int s = d_seg_start[b];
    int e = (s < 0) ? 0 : d_seg_end[b];
    if (s < 0) s = 0;

    float sum = 0.f, mx = -CUDART_INF_F;
    float m0 = -CUDART_INF_F, dn0 = 0.f, ac0 = 0.f;
    float m1 = -CUDART_INF_F, dn1 = 0.f, ac1 = 0.f;

    int n = s;
    for (; n + 2 <= e; n += 2) {
        float xv0 = __ldg(x + (size_t)n * H + j);
        float g0  = d_gate[n];
        float xv1 = __ldg(x + (size_t)(n + 1) * H + j);
        float g1  = d_gate[n + 1];
        sum += xv0 + xv1;
        mx = fmaxf(mx, fmaxf(xv0, xv1));
        if (g0 > m0) { float sc = __expf(m0 - g0); dn0 *= sc; ac0 *= sc; m0 = g0; }
        float e0 = __expf(g0 - m0); dn0 += e0; ac0 = fmaf(e0, xv0, ac0);
        if (g1 > m1) { float sc = __expf(m1 - g1); dn1 *= sc; ac1 *= sc; m1 = g1; }
        float e1 = __expf(g1 - m1); dn1 += e1; ac1 = fmaf(e1, xv1, ac1);
    }
    if (n < e) {
        float xv = __ldg(x + (size_t)n * H + j);
        float g  = d_gate[n];
        sum += xv; mx = fmaxf(mx, xv);
        if (g > m0) { float sc = __expf(m0 - g); dn0 *= sc; ac0 *= sc; m0 = g; }
        float ev = __expf(g - m0); dn0 += ev; ac0 = fmaf(ev, xv, ac0);
    }

    int cnt = e - s;
    float denom = 0.f, acc = 0.f;
    if (cnt > 0) {
        float M  = fmaxf(m0, m1);
        float s0 = (m0 > -CUDART_INF_F) ? __expf(m0 - M) : 0.f;
        float s1 = (m1 > -CUDART_INF_F) ? __expf(m1 - M) : 0.f;
        denom = dn0 * s0 + dn1 * s1;
        acc   = ac0 * s0 + ac1 * s1;
    }
    float* o = out + (size_t)b * (3 * H);
    o[j]         = sum / fmaxf((float)cnt, 1.f);
    o[H + j]     = mx;
    o[2 * H + j] = (cnt > 0) ? (acc / denom) : 0.f;
}

// ---------------------------------------------------------------------------
extern "C" void kernel_launch(void* const* d_in, const int* in_sizes, int n_in,
                              void* d_out, int out_size) {
    const float* x  = (const float*)d_in[0];
    const float* W1 = (const float*)d_in[1];
    const float* b1 = (const float*)d_in[2];
    const float* W2 = (const float*)d_in[3];
    const int*   bi = (const int*)d_in[5];

    const int N = in_sizes[5];
    const int B = out_size / (3 * H);
    float* out = (float*)d_out;

    static int inited = 0;
    static int sms = 148;
    if (!inited) {
        cudaFuncSetAttribute(gate_mma_kernel,
                             cudaFuncAttributeMaxDynamicSharedMemorySize, SMEM_TOTAL);
        int dev = 0;
        cudaGetDevice(&dev);
        cudaDeviceGetAttribute(&sms, cudaDevAttrMultiProcessorCount, dev);
        inited = 1;
    }

    const int numTiles = (N + 63) / 64;
    const int gateGrid = (2 * sms < numTiles) ? 2 * sms : numTiles;

    init_bounds_kernel<<<(B + 255) / 256, 256>>>(B);
    bounds_kernel<<<(N + 255) / 256, 256>>>(bi, N);
    prep_w1_kernel<<<(H * H + 255) / 256, 256>>>(W1);
    gate_mma_kernel<<<gateGrid, 256, SMEM_TOTAL>>>(x, b1, W2, N);
    reduce_kernel<<<B, H>>>(x, out);
}